// round 4
// baseline (speedup 1.0000x reference)
#include <cuda_runtime.h>
#include <mma.h>
#include <math.h>

using namespace nvcuda;

#define BSZ   64
#define TSZ   512
#define INSZ  1024
#define HIDSZ 1024
#define BH    65536                        // 64*1024
static constexpr size_t TBH = 33554432ull; // 512*64*1024

#define NCTA_REC 96                        // persistent grid, 1 CTA/SM

// Scratch (device globals — no allocations allowed)
__device__ float g_gates[3ull * 512ull * 64ull * 1024ull]; // [gate][t*B+b][hid]
__device__ float g_hw[3 * BH];                             // per-step h@W_h per gate

// Grid barrier state
__device__ unsigned g_bar_cnt = 0;
__device__ unsigned g_bar_gen = 0;

__device__ __forceinline__ unsigned ld_acquire_gpu(const unsigned* p) {
    unsigned v;
    asm volatile("ld.acquire.gpu.u32 %0, [%1];" : "=r"(v) : "l"(p) : "memory");
    return v;
}
__device__ __forceinline__ void st_release_gpu(unsigned* p, unsigned v) {
    asm volatile("st.release.gpu.u32 [%0], %1;" :: "l"(p), "r"(v) : "memory");
}

// Sense-free barrier: caller supplies the absolute target generation.
__device__ __forceinline__ void grid_barrier(unsigned target_gen) {
    __syncthreads();
    if (threadIdx.x == 0) {
        __threadfence();   // release my writes (emits gpu-scope fence -> L1 inval)
        unsigned old = atomicAdd(&g_bar_cnt, 1u);
        if (old == NCTA_REC - 1u) {
            g_bar_cnt = 0u;                       // ordered before release below
            st_release_gpu(&g_bar_gen, target_gen);
        } else {
            while (ld_acquire_gpu(&g_bar_gen) != target_gen) __nanosleep(64);
        }
        __threadfence();   // acquire side: invalidate L1 so ALL warps see remote writes
    }
    __syncthreads();
}

// ---------------------------------------------------------------------------
// Stage 1: gates[g][m][n] = sum_k x[m,k] * W_g[k,n]   (m = t*64 + b)
// x element for row m: inputs[(b*T + t)*IN + k]  (inputs is [B,T,IN])
// tf32 conversion hoisted into the smem stores.
// ---------------------------------------------------------------------------
__global__ void stage1_kernel(const float* __restrict__ x,
                              const float* __restrict__ Wr,
                              const float* __restrict__ Wz,
                              const float* __restrict__ Wn) {
    __shared__ __align__(32) float As[64][40];
    __shared__ __align__(32) float Bs[32][72];

    const int nb = blockIdx.x;          // 0..47 : gate*16 + ntile
    const int mb = blockIdx.y;          // 0..511
    const int gate = nb >> 4;
    const int col0 = (nb & 15) << 6;
    const float* W = (gate == 0) ? Wr : ((gate == 1) ? Wz : Wn);
    const int m0 = mb << 6;

    const int tid  = threadIdx.x;
    const int warp = tid >> 5;
    const int fr   = warp & 3;
    const int fc0  = (warp >> 2) << 1;

    wmma::fragment<wmma::accumulator, 16, 16, 8, float> acc[2];
    wmma::fill_fragment(acc[0], 0.0f);
    wmma::fill_fragment(acc[1], 0.0f);

    const int ar = tid >> 3;
    const int ac = (tid & 7) << 2;
    const int br = tid >> 4;
    const int bc = (tid & 15) << 2;

    for (int k0 = 0; k0 < INSZ; k0 += 32) {
#pragma unroll
        for (int rr = 0; rr < 2; rr++) {
            int m = m0 + ar + rr * 32;
            int t = m >> 6;
            int b = m & 63;
            float4 v = *(const float4*)(x + ((size_t)b * TSZ + t) * INSZ + k0 + ac);
            float* dst = &As[ar + rr * 32][ac];
            dst[0] = wmma::__float_to_tf32(v.x); dst[1] = wmma::__float_to_tf32(v.y);
            dst[2] = wmma::__float_to_tf32(v.z); dst[3] = wmma::__float_to_tf32(v.w);
        }
#pragma unroll
        for (int rr = 0; rr < 2; rr++) {
            float4 v = *(const float4*)(W + (size_t)(k0 + br + rr * 16) * HIDSZ + col0 + bc);
            float* dst = &Bs[br + rr * 16][bc];
            dst[0] = wmma::__float_to_tf32(v.x); dst[1] = wmma::__float_to_tf32(v.y);
            dst[2] = wmma::__float_to_tf32(v.z); dst[3] = wmma::__float_to_tf32(v.w);
        }
        __syncthreads();

#pragma unroll
        for (int kk = 0; kk < 4; kk++) {
            wmma::fragment<wmma::matrix_a, 16, 16, 8, wmma::precision::tf32, wmma::row_major> a;
            wmma::load_matrix_sync(a, &As[fr * 16][kk * 8], 40);
#pragma unroll
            for (int j = 0; j < 2; j++) {
                wmma::fragment<wmma::matrix_b, 16, 16, 8, wmma::precision::tf32, wmma::row_major> bfr;
                wmma::load_matrix_sync(bfr, &Bs[kk * 8][(fc0 + j) * 16], 72);
                wmma::mma_sync(acc[j], a, bfr, acc[j]);
            }
        }
        __syncthreads();
    }

#pragma unroll
    for (int j = 0; j < 2; j++) {
        float* p = g_gates + (size_t)gate * TBH
                 + (size_t)(m0 + fr * 16) * HIDSZ + col0 + (fc0 + j) * 16;
        wmma::store_matrix_sync(p, acc[j], HIDSZ, wmma::mem_row_major);
    }
}

// ---------------------------------------------------------------------------
// Persistent recurrence. 96 CTAs x 256 threads, dynamic smem:
//   Ws[1024][36]  resident W slice (tf32, loaded once)        147456 B
//   hb[8][64][36] h tiles: 2 pipeline stages x 4 K-groups       73728 B
// Phase A: hW = h_{t-1} @ W (gate-split + 4-way K-split, 32x32 warp tiles)
// Phase B: pointwise GRU update -> out
// ---------------------------------------------------------------------------
#define SMEM_WS_FLOATS  (1024 * 36)
#define SMEM_REC_BYTES  (147456 + 73728)

__global__ __launch_bounds__(256, 1)
void recur_kernel(const float* __restrict__ Wr,
                  const float* __restrict__ Wz,
                  const float* __restrict__ Wn,
                  const float* __restrict__ b_ir, const float* __restrict__ b_hr,
                  const float* __restrict__ b_iz, const float* __restrict__ b_hz,
                  const float* __restrict__ b_in, const float* __restrict__ b_hn,
                  float* __restrict__ out, int write_hfinal) {
    extern __shared__ __align__(16) char smem[];
    float (*Ws)[36] = (float(*)[36])smem;                       // [1024][36]
    float (*hb)[64][36] = (float(*)[64][36])(smem + 147456);    // [8][64][36]
    float* red = (float*)(smem + 147456);                        // reduce scratch (reuse)

    const int cta  = blockIdx.x;
    const int tid  = threadIdx.x;
    const int warp = tid >> 5;
    const int grp  = warp >> 1;                  // K-group 0..3 (k in [grp*256, +256))
    const int wr   = warp & 1;                   // row half (32 batch rows)

    const int gate = cta >> 5;                   // 0..2
    const int col0 = (cta & 31) << 5;            // 32-col tile
    const float* W = (gate == 0) ? Wr : ((gate == 1) ? Wz : Wn);

    // Barrier generation base (replay-safe: read before any barrier can fire)
    __shared__ unsigned s_gen0;
    if (tid == 0) s_gen0 = *(volatile unsigned*)&g_bar_gen;

    // Load resident W slice (1024 x 32), tf32-rounded. 128 floats/thread.
    for (int q = 0; q < 32; q++) {
        int idx = tid + q * 256;                 // 0..8191 float4s
        int k   = idx >> 3;
        int c4  = (idx & 7) << 2;
        float4 v = *(const float4*)(W + (size_t)k * HIDSZ + col0 + c4);
        float* dst = &Ws[k][c4];
        dst[0] = wmma::__float_to_tf32(v.x); dst[1] = wmma::__float_to_tf32(v.y);
        dst[2] = wmma::__float_to_tf32(v.z); dst[3] = wmma::__float_to_tf32(v.w);
    }
    __syncthreads();
    unsigned gen = s_gen0;

    // Phase-B per-thread fixed column -> biases in registers
    const int i0 = cta * 256 + tid;              // stride 24576 = 24*1024
    const int jj = i0 & 1023;
    const float vb_ir = b_ir[jj], vb_hr = b_hr[jj];
    const float vb_iz = b_iz[jj], vb_hz = b_hz[jj];
    const float vb_in = b_in[jj], vb_hn = b_hn[jj];

    for (int t = 0; t < TSZ; t++) {
        if (t > 0) {
            // ============ Phase A: hW tile [64 x 32] for this gate ============
            const float* h = out + (size_t)(t - 1) * BH;

            wmma::fragment<wmma::accumulator, 16, 16, 8, float> acc[2][2];
#pragma unroll
            for (int mi = 0; mi < 2; mi++)
#pragma unroll
                for (int ni = 0; ni < 2; ni++) wmma::fill_fragment(acc[mi][ni], 0.0f);

            // Preload iteration 0: 4 tiles (one per K-group), each [64 x 32k]
            {
#pragma unroll
                for (int q = 0; q < 8; q++) {
                    int gidx = tid + q * 256;        // 0..2047 float4s
                    int tg   = gidx >> 9;            // group 0..3
                    int idx  = gidx & 511;
                    int row  = idx >> 3;
                    int c4   = (idx & 7) << 2;
                    float4 v = *(const float4*)(h + (size_t)row * HIDSZ + tg * 256 + c4);
                    float* dst = &hb[tg][row][c4];
                    dst[0] = wmma::__float_to_tf32(v.x); dst[1] = wmma::__float_to_tf32(v.y);
                    dst[2] = wmma::__float_to_tf32(v.z); dst[3] = wmma::__float_to_tf32(v.w);
                }
            }
            __syncthreads();

            for (int it = 0; it < 8; it++) {
                // stage loads for it+1 into registers (latency overlapped w/ compute)
                float4 st[8];
                if (it < 7) {
#pragma unroll
                    for (int q = 0; q < 8; q++) {
                        int gidx = tid + q * 256;
                        int tg   = gidx >> 9;
                        int idx  = gidx & 511;
                        int row  = idx >> 3;
                        int c4   = (idx & 7) << 2;
                        st[q] = *(const float4*)(h + (size_t)row * HIDSZ
                                                 + tg * 256 + (it + 1) * 32 + c4);
                    }
                }

                // compute current buffer
                {
                    const float (*A)[36] = hb[(it & 1) * 4 + grp];
                    const int kbase = grp * 256 + it * 32;
#pragma unroll
                    for (int kk = 0; kk < 4; kk++) {
                        wmma::fragment<wmma::matrix_a, 16, 16, 8, wmma::precision::tf32, wmma::row_major> a0, a1;
                        wmma::load_matrix_sync(a0, &A[wr * 32][kk * 8], 36);
                        wmma::load_matrix_sync(a1, &A[wr * 32 + 16][kk * 8], 36);
                        wmma::fragment<wmma::matrix_b, 16, 16, 8, wmma::precision::tf32, wmma::row_major> b0, b1;
                        wmma::load_matrix_sync(b0, &Ws[kbase + kk * 8][0],  36);
                        wmma::load_matrix_sync(b1, &Ws[kbase + kk * 8][16], 36);
                        wmma::mma_sync(acc[0][0], a0, b0, acc[0][0]);
                        wmma::mma_sync(acc[0][1], a0, b1, acc[0][1]);
                        wmma::mma_sync(acc[1][0], a1, b0, acc[1][0]);
                        wmma::mma_sync(acc[1][1], a1, b1, acc[1][1]);
                    }
                }

                if (it < 7) {
#pragma unroll
                    for (int q = 0; q < 8; q++) {
                        int gidx = tid + q * 256;
                        int tg   = gidx >> 9;
                        int idx  = gidx & 511;
                        int row  = idx >> 3;
                        int c4   = (idx & 7) << 2;
                        float* dst = &hb[((it + 1) & 1) * 4 + tg][row][c4];
                        dst[0] = wmma::__float_to_tf32(st[q].x);
                        dst[1] = wmma::__float_to_tf32(st[q].y);
                        dst[2] = wmma::__float_to_tf32(st[q].z);
                        dst[3] = wmma::__float_to_tf32(st[q].w);
                    }
                }
                __syncthreads();
            }

            // K-split reduction: groups 1..3 publish partials, group 0 sums.
            if (grp > 0) {
                float* s = red + (size_t)((grp - 1) * 2 + wr) * 1024;   // 32x32 region
#pragma unroll
                for (int mi = 0; mi < 2; mi++)
#pragma unroll
                    for (int ni = 0; ni < 2; ni++)
                        wmma::store_matrix_sync(s + mi * 16 * 32 + ni * 16,
                                                acc[mi][ni], 32, wmma::mem_row_major);
            }
            __syncthreads();
            if (grp == 0) {
#pragma unroll
                for (int src = 0; src < 3; src++) {
                    const float* s = red + (size_t)(src * 2 + wr) * 1024;
#pragma unroll
                    for (int mi = 0; mi < 2; mi++)
#pragma unroll
                        for (int ni = 0; ni < 2; ni++) {
                            wmma::fragment<wmma::accumulator, 16, 16, 8, float> p;
                            wmma::load_matrix_sync(p, s + mi * 16 * 32 + ni * 16, 32,
                                                   wmma::mem_row_major);
#pragma unroll
                            for (int e = 0; e < p.num_elements; e++)
                                acc[mi][ni].x[e] += p.x[e];
                        }
                }
                float* pw = g_hw + (size_t)gate * BH + col0;
#pragma unroll
                for (int mi = 0; mi < 2; mi++)
#pragma unroll
                    for (int ni = 0; ni < 2; ni++)
                        wmma::store_matrix_sync(pw + (size_t)(wr * 32 + mi * 16) * HIDSZ + ni * 16,
                                                acc[mi][ni], HIDSZ, wmma::mem_row_major);
            }
            gen++; grid_barrier(gen);
        }

        // ============ Phase B: pointwise GRU update ============
        {
            const size_t toff = (size_t)t * BH;
            const float* hprev = out + (size_t)(t - 1) * BH;
            float* hout = out + toff;

            for (int i = i0; i < BH; i += NCTA_REC * 256) {
                float gr = g_gates[toff + i]              + vb_ir;
                float gz = g_gates[TBH + toff + i]        + vb_iz;
                float gn = g_gates[2ull * TBH + toff + i] + vb_in;

                float hr = vb_hr, hz = vb_hz, hn = vb_hn, hp = 0.0f;
                if (t > 0) {
                    hr += g_hw[i];
                    hz += g_hw[BH + i];
                    hn += g_hw[2 * BH + i];
                    hp  = hprev[i];
                }

                float r = 1.0f / (1.0f + expf(-(gr + hr)));
                float z = 1.0f / (1.0f + expf(-(gz + hz)));
                float n = tanhf(gn + r * hn);
                float hnew = (1.0f - z) * n + z * hp;

                hout[i] = hnew;
                if (t == TSZ - 1 && write_hfinal) out[TBH + i] = hnew;
            }
        }
        gen++; grid_barrier(gen);
    }
}

// ---------------------------------------------------------------------------
extern "C" void kernel_launch(void* const* d_in, const int* in_sizes, int n_in,
                              void* d_out, int out_size) {
    const float* x    = (const float*)d_in[0];
    const float* W_ir = (const float*)d_in[1];
    const float* b_ir = (const float*)d_in[2];
    const float* W_hr = (const float*)d_in[3];
    const float* b_hr = (const float*)d_in[4];
    const float* W_iz = (const float*)d_in[5];
    const float* b_iz = (const float*)d_in[6];
    const float* W_hz = (const float*)d_in[7];
    const float* b_hz = (const float*)d_in[8];
    const float* W_in = (const float*)d_in[9];
    const float* b_in = (const float*)d_in[10];
    const float* W_hn = (const float*)d_in[11];
    const float* b_hn = (const float*)d_in[12];
    float* out = (float*)d_out;

    const int has_hfinal = ((size_t)out_size >= TBH + (size_t)BH) ? 1 : 0;

    static int attr_done = 0;
    if (!attr_done) {
        cudaFuncSetAttribute(recur_kernel,
                             cudaFuncAttributeMaxDynamicSharedMemorySize,
                             SMEM_REC_BYTES);
        attr_done = 1;
    }

    stage1_kernel<<<dim3(48, 512), 256>>>(x, W_ir, W_iz, W_in);

    recur_kernel<<<NCTA_REC, 256, SMEM_REC_BYTES>>>(
        W_hr, W_hz, W_hn,
        b_ir, b_hr, b_iz, b_hz, b_in, b_hn,
        out, has_hfinal);
}

// round 5
// speedup vs baseline: 1.2495x; 1.2495x over previous
#include <cuda_runtime.h>
#include <mma.h>
#include <math.h>

using namespace nvcuda;

#define TSZ   512
#define INSZ  1024
#define HIDSZ 1024
#define BH    65536                        // 64*1024
static constexpr size_t TBH = 33554432ull; // 512*64*1024

#define NCTA  64
#define NTHR  256

// Device-global scratch (no allocations allowed)
__device__ float g_gates[3ull * TBH];          // stage1 output [gate][t*64+b][hid]
__device__ float g_Wt[3ull * 1024 * 1024];     // tf32-rounded W_hr|W_hz|W_hn
__device__ float g_ht[2][BH];                  // tf32-rounded h ping-pong
__device__ unsigned g_bar_cnt = 0;
__device__ unsigned g_bar_gen = 0;

// ---------------------------------------------------------------------------
// Fence-free grid barrier. Safe because every cross-CTA location is
// write-once-read-later at fresh addresses (no stale L1 lines possible);
// ordering/visibility carried by the release-atomic + acquire-load pair.
// ---------------------------------------------------------------------------
__device__ __forceinline__ void grid_barrier(unsigned target) {
    __syncthreads();
    if (threadIdx.x == 0) {
        unsigned old;
        asm volatile("atom.acq_rel.gpu.add.u32 %0, [%1], %2;"
                     : "=r"(old) : "l"(&g_bar_cnt), "r"(1u) : "memory");
        if (old == NCTA - 1u) {
            asm volatile("st.relaxed.gpu.u32 [%0], %1;" :: "l"(&g_bar_cnt), "r"(0u) : "memory");
            asm volatile("st.release.gpu.u32 [%0], %1;" :: "l"(&g_bar_gen), "r"(target) : "memory");
        } else {
            unsigned v;
            do {
                asm volatile("ld.acquire.gpu.u32 %0, [%1];" : "=r"(v) : "l"(&g_bar_gen) : "memory");
            } while ((int)(v - target) < 0);
        }
    }
    __syncthreads();
}

__device__ __forceinline__ void cp16(void* sdst, const void* gsrc) {
    unsigned s = (unsigned)__cvta_generic_to_shared(sdst);
    asm volatile("cp.async.cg.shared.global [%0], [%1], 16;" :: "r"(s), "l"(gsrc));
}
#define CP_COMMIT() asm volatile("cp.async.commit_group;")
#define CP_WAIT2()  asm volatile("cp.async.wait_group 2;")

// ---------------------------------------------------------------------------
// W pre-conversion: fp32 -> tf32(RN) bits, concatenated [Wr|Wz|Wn]
// ---------------------------------------------------------------------------
__global__ void wconv_kernel(const float* __restrict__ Wr,
                             const float* __restrict__ Wz,
                             const float* __restrict__ Wn) {
    int i = blockIdx.x * 256 + threadIdx.x;    // 0..786431 (float4 index)
    int g = i >> 18;                            // 262144 float4 per matrix
    int o = i & 262143;
    const float* src = (g == 0) ? Wr : ((g == 1) ? Wz : Wn);
    float4 v = ((const float4*)src)[o];
    v.x = wmma::__float_to_tf32(v.x); v.y = wmma::__float_to_tf32(v.y);
    v.z = wmma::__float_to_tf32(v.z); v.w = wmma::__float_to_tf32(v.w);
    ((float4*)(g_Wt + (size_t)g * 1048576))[o] = v;
}

// ---------------------------------------------------------------------------
// Stage 1 (unchanged): gates[g][m][n] = sum_k x[m,k] * W_g[k,n], m = t*64+b
// ---------------------------------------------------------------------------
__global__ void stage1_kernel(const float* __restrict__ x,
                              const float* __restrict__ Wr,
                              const float* __restrict__ Wz,
                              const float* __restrict__ Wn) {
    __shared__ __align__(32) float As[64][40];
    __shared__ __align__(32) float Bs[32][72];

    const int nb = blockIdx.x;
    const int mb = blockIdx.y;
    const int gate = nb >> 4;
    const int col0 = (nb & 15) << 6;
    const float* W = (gate == 0) ? Wr : ((gate == 1) ? Wz : Wn);
    const int m0 = mb << 6;

    const int tid  = threadIdx.x;
    const int warp = tid >> 5;
    const int fr   = warp & 3;
    const int fc0  = (warp >> 2) << 1;

    wmma::fragment<wmma::accumulator, 16, 16, 8, float> acc[2];
    wmma::fill_fragment(acc[0], 0.0f);
    wmma::fill_fragment(acc[1], 0.0f);

    const int ar = tid >> 3;
    const int ac = (tid & 7) << 2;
    const int br = tid >> 4;
    const int bc = (tid & 15) << 2;

    for (int k0 = 0; k0 < INSZ; k0 += 32) {
#pragma unroll
        for (int rr = 0; rr < 2; rr++) {
            int m = m0 + ar + rr * 32;
            int t = m >> 6;
            int b = m & 63;
            float4 v = *(const float4*)(x + ((size_t)b * TSZ + t) * INSZ + k0 + ac);
            float* dst = &As[ar + rr * 32][ac];
            dst[0] = wmma::__float_to_tf32(v.x); dst[1] = wmma::__float_to_tf32(v.y);
            dst[2] = wmma::__float_to_tf32(v.z); dst[3] = wmma::__float_to_tf32(v.w);
        }
#pragma unroll
        for (int rr = 0; rr < 2; rr++) {
            float4 v = *(const float4*)(W + (size_t)(k0 + br + rr * 16) * HIDSZ + col0 + bc);
            float* dst = &Bs[br + rr * 16][bc];
            dst[0] = wmma::__float_to_tf32(v.x); dst[1] = wmma::__float_to_tf32(v.y);
            dst[2] = wmma::__float_to_tf32(v.z); dst[3] = wmma::__float_to_tf32(v.w);
        }
        __syncthreads();

#pragma unroll
        for (int kk = 0; kk < 4; kk++) {
            wmma::fragment<wmma::matrix_a, 16, 16, 8, wmma::precision::tf32, wmma::row_major> a;
            wmma::load_matrix_sync(a, &As[fr * 16][kk * 8], 40);
#pragma unroll
            for (int j = 0; j < 2; j++) {
                wmma::fragment<wmma::matrix_b, 16, 16, 8, wmma::precision::tf32, wmma::row_major> bfr;
                wmma::load_matrix_sync(bfr, &Bs[kk * 8][(fc0 + j) * 16], 72);
                wmma::mma_sync(acc[j], a, bfr, acc[j]);
            }
        }
        __syncthreads();
    }

#pragma unroll
    for (int j = 0; j < 2; j++) {
        float* p = g_gates + (size_t)gate * TBH
                 + (size_t)(m0 + fr * 16) * HIDSZ + col0 + (fc0 + j) * 16;
        wmma::store_matrix_sync(p, acc[j], HIDSZ, wmma::mem_row_major);
    }
}

// ---------------------------------------------------------------------------
// Persistent recurrence: 64 CTAs x 256 threads, owner-computes, ONE grid
// barrier per step. CTA c owns output cols [16c,16c+16) of all 3 gates.
// GEMM [64x1024] @ [1024x48], 8 warps = 2 K-groups x 4 m16-rows.
// Smem (dynamic, 126976 B):
//   hb: 4 stages x 2 grp x [64][36]  (73728 B)   | pre aliases stage 0
//   Wb: 4 stages x 2 grp x [32][52]  (53248 B)   | red aliases stage 0
// ---------------------------------------------------------------------------
#define SMEM_REC_BYTES 126976

__global__ __launch_bounds__(NTHR, 1)
void recur_kernel(const float* __restrict__ b_ir, const float* __restrict__ b_hr,
                  const float* __restrict__ b_iz, const float* __restrict__ b_hz,
                  const float* __restrict__ b_in, const float* __restrict__ b_hn,
                  float* __restrict__ out, int write_hfinal) {
    extern __shared__ __align__(16) float sm[];
    float* hb = sm;            // 4*2*64*36 = 18432 floats
    float* Wb = sm + 18432;    // 4*2*32*52 = 13312 floats
    float* red = Wb;           // 64*48 = 3072 floats (fits in Wb stage 0: 3328)
    float* pre = sm;           // 64*48 = 3072 floats (fits in hb stage 0: 4608)

    const int cta  = blockIdx.x;
    const int tid  = threadIdx.x;
    const int wid  = tid >> 5;
    const int kgrp = wid >> 2;            // 0..1 : K range [kgrp*512, +512)
    const int mrow = wid & 3;             // m16 slice rows [16*mrow, +16)
    const int col0 = cta << 4;

    __shared__ unsigned s_gen0;
    if (tid == 0) s_gen0 = *(volatile unsigned*)&g_bar_gen;
    __syncthreads();
    const unsigned gen0 = s_gen0;

    // pointwise: fixed column per thread -> biases in registers
    const int c_pb = tid & 15;
    const int r_pb = tid >> 4;
    const int jcol = col0 + c_pb;
    const float vb_ir = b_ir[jcol], vb_hr = b_hr[jcol];
    const float vb_iz = b_iz[jcol], vb_hz = b_hz[jcol];
    const float vb_in = b_in[jcol], vb_hn = b_hn[jcol];

    for (int t = 0; t < TSZ; t++) {
        if (t > 0) {
            const float* hsrc = g_ht[(t - 1) & 1];

            wmma::fragment<wmma::accumulator, 16, 16, 8, float> acc[3];
#pragma unroll
            for (int g = 0; g < 3; g++) wmma::fill_fragment(acc[g], 0.0f);

            // ---- issue helper (inlined twice) ----
#define ISSUE_CHUNK(c)                                                          \
            {                                                                   \
                int kofs = (c) * 32;                                            \
                _Pragma("unroll")                                               \
                for (int q = 0; q < 4; q++) {                                   \
                    int o = tid + q * 256;                                      \
                    int grp = o >> 9, idx = o & 511;                            \
                    int row = idx >> 3, c4 = (idx & 7) << 2;                    \
                    cp16(hb + (((c) & 3) * 2 + grp) * 2304 + row * 36 + c4,     \
                         hsrc + (size_t)row * 1024 + grp * 512 + kofs + c4);    \
                }                                                               \
                _Pragma("unroll")                                               \
                for (int q = 0; q < 3; q++) {                                   \
                    int o = tid + q * 256;                                      \
                    int grp = (o >= 384) ? 1 : 0;                               \
                    int idx = o - grp * 384;                                    \
                    int row = idx / 12, cw = (idx % 12) << 2;                   \
                    int gate = cw >> 4;                                         \
                    cp16(Wb + (((c) & 3) * 2 + grp) * 1664 + row * 52 + cw,     \
                         g_Wt + (size_t)gate * 1048576                          \
                              + (size_t)(grp * 512 + kofs + row) * 1024         \
                              + col0 + (cw & 15));                              \
                }                                                               \
            }

            ISSUE_CHUNK(0); CP_COMMIT();
            ISSUE_CHUNK(1); CP_COMMIT();

            for (int it = 0; it < 16; it++) {
                if (it + 2 < 16) ISSUE_CHUNK(it + 2);
                CP_COMMIT();
                CP_WAIT2();
                __syncthreads();

                const float* A  = hb + ((it & 3) * 2 + kgrp) * 2304 + (mrow * 16) * 36;
                const float* Bp = Wb + ((it & 3) * 2 + kgrp) * 1664;
#pragma unroll
                for (int kk = 0; kk < 4; kk++) {
                    wmma::fragment<wmma::matrix_a, 16, 16, 8, wmma::precision::tf32, wmma::row_major> a;
                    wmma::load_matrix_sync(a, A + kk * 8, 36);
#pragma unroll
                    for (int g = 0; g < 3; g++) {
                        wmma::fragment<wmma::matrix_b, 16, 16, 8, wmma::precision::tf32, wmma::row_major> bf;
                        wmma::load_matrix_sync(bf, Bp + (kk * 8) * 52 + g * 16, 52);
                        wmma::mma_sync(acc[g], a, bf, acc[g]);
                    }
                }
            }
#undef ISSUE_CHUNK

            // K-split reduction: kgrp1 publishes partials, kgrp0 combines.
            if (kgrp == 1) {
#pragma unroll
                for (int g = 0; g < 3; g++)
                    wmma::store_matrix_sync(red + (mrow * 16) * 48 + g * 16,
                                            acc[g], 48, wmma::mem_row_major);
            }
            __syncthreads();
            if (kgrp == 0) {
#pragma unroll
                for (int g = 0; g < 3; g++) {
                    wmma::fragment<wmma::accumulator, 16, 16, 8, float> p;
                    wmma::load_matrix_sync(p, red + (mrow * 16) * 48 + g * 16, 48,
                                           wmma::mem_row_major);
#pragma unroll
                    for (int e = 0; e < p.num_elements; e++) acc[g].x[e] += p.x[e];
                    wmma::store_matrix_sync(pre + (mrow * 16) * 48 + g * 16,
                                            acc[g], 48, wmma::mem_row_major);
                }
            }
            __syncthreads();
        }

        // ---- pointwise GRU update (owned 64 rows x 16 cols) ----
        {
            const size_t toff = (size_t)t * BH;
            float* hw = out + toff;
            const float* hp_ptr = out + toff - BH;   // valid when t>0
#pragma unroll
            for (int q = 0; q < 4; q++) {
                int row = r_pb + q * 16;
                int gi  = row * 1024 + jcol;

                float gr = g_gates[toff + gi]              + vb_ir;
                float gz = g_gates[TBH + toff + gi]        + vb_iz;
                float gn = g_gates[2ull * TBH + toff + gi] + vb_in;

                float hr = vb_hr, hz = vb_hz, hn = vb_hn, hp = 0.0f;
                if (t > 0) {
                    hr += pre[row * 48 + c_pb];
                    hz += pre[row * 48 + 16 + c_pb];
                    hn += pre[row * 48 + 32 + c_pb];
                    hp  = hp_ptr[gi];
                }

                float r = 1.0f / (1.0f + expf(-(gr + hr)));
                float z = 1.0f / (1.0f + expf(-(gz + hz)));
                float n = tanhf(gn + r * hn);
                float hnew = (1.0f - z) * n + z * hp;

                hw[gi] = hnew;
                g_ht[t & 1][gi] = wmma::__float_to_tf32(hnew);
                if (t == TSZ - 1 && write_hfinal) out[TBH + gi] = hnew;
            }
        }

        grid_barrier(gen0 + (unsigned)t + 1u);
    }
}

// ---------------------------------------------------------------------------
extern "C" void kernel_launch(void* const* d_in, const int* in_sizes, int n_in,
                              void* d_out, int out_size) {
    const float* x    = (const float*)d_in[0];
    const float* W_ir = (const float*)d_in[1];
    const float* b_ir = (const float*)d_in[2];
    const float* W_hr = (const float*)d_in[3];
    const float* b_hr = (const float*)d_in[4];
    const float* W_iz = (const float*)d_in[5];
    const float* b_iz = (const float*)d_in[6];
    const float* W_hz = (const float*)d_in[7];
    const float* b_hz = (const float*)d_in[8];
    const float* W_in = (const float*)d_in[9];
    const float* b_in = (const float*)d_in[10];
    const float* W_hn = (const float*)d_in[11];
    const float* b_hn = (const float*)d_in[12];
    float* out = (float*)d_out;

    const int has_hfinal = ((size_t)out_size >= TBH + (size_t)BH) ? 1 : 0;

    static int attr_done = 0;
    if (!attr_done) {
        cudaFuncSetAttribute(recur_kernel,
                             cudaFuncAttributeMaxDynamicSharedMemorySize,
                             SMEM_REC_BYTES);
        attr_done = 1;
    }

    wconv_kernel<<<3072, 256>>>(W_hr, W_hz, W_hn);
    stage1_kernel<<<dim3(48, 512), 256>>>(x, W_ir, W_iz, W_in);
    recur_kernel<<<NCTA, NTHR, SMEM_REC_BYTES>>>(
        b_ir, b_hr, b_iz, b_hz, b_in, b_hn, out, has_hfinal);
}

// round 6
// speedup vs baseline: 1.4874x; 1.1904x over previous
#include <cuda_runtime.h>
#include <mma.h>
#include <math.h>

using namespace nvcuda;

#define TSZ   512
#define INSZ  1024
#define HIDSZ 1024
#define BH    65536                        // 64*1024
static constexpr size_t TBH = 33554432ull; // 512*64*1024

#define NCTA  64
#define NTHR  256

// Device-global scratch (no allocations allowed)
__device__ float g_gates[3ull * TBH];           // stage1 out [gate][t*64+b][hid]
__device__ float g_Wall[6ull * 1048576];        // tf32 W: [hr|hz|hn|ir|iz|in]
__device__ float g_xt[32768ull * 1024];         // tf32 x, time-major [t*64+b][k]
__device__ float g_ht[2][BH];                   // tf32 h ping-pong
__device__ unsigned g_bar_cnt = 0;
__device__ unsigned g_bar_gen = 0;

// ---------------------------------------------------------------------------
__device__ __forceinline__ void cp16(void* sdst, const void* gsrc) {
    unsigned s = (unsigned)__cvta_generic_to_shared(sdst);
    asm volatile("cp.async.cg.shared.global [%0], [%1], 16;" :: "r"(s), "l"(gsrc));
}
#define CP_COMMIT() asm volatile("cp.async.commit_group;")
#define CP_WAIT0()  asm volatile("cp.async.wait_group 0;")

// ---------------------------------------------------------------------------
// Prep: tf32-round weights; tf32-round + time-major-transpose x.
// ---------------------------------------------------------------------------
__global__ void wconv_kernel(const float* __restrict__ src, int which) {
    int i = blockIdx.x * 256 + threadIdx.x;     // 0..262143 float4
    float4 v = ((const float4*)src)[i];
    v.x = wmma::__float_to_tf32(v.x); v.y = wmma::__float_to_tf32(v.y);
    v.z = wmma::__float_to_tf32(v.z); v.w = wmma::__float_to_tf32(v.w);
    ((float4*)(g_Wall + (size_t)which * 1048576))[i] = v;
}

__global__ void xprep_kernel(const float* __restrict__ x) {
    int m = blockIdx.x;                          // 0..32767 : m = t*64+b
    int t = m >> 6, b = m & 63;
    int c = threadIdx.x;                         // float4 col 0..255
    float4 v = ((const float4*)(x + ((size_t)b * TSZ + t) * INSZ))[c];
    v.x = wmma::__float_to_tf32(v.x); v.y = wmma::__float_to_tf32(v.y);
    v.z = wmma::__float_to_tf32(v.z); v.w = wmma::__float_to_tf32(v.w);
    ((float4*)(g_xt + (size_t)m * 1024))[c] = v;
}

// ---------------------------------------------------------------------------
// Stage 1 v2: gates[g][m][n] = xt[m,:] @ W_g[:,n].  Tile 128m x 64n, K-chunk 32,
// cp.async double-buffered, 256 thr, 8 warps = 4 mrow(32) x 2 ncol(32).
// Dyn smem: 2 stages x (A[128][36] + B[32][68]) = 54272 B.
// ---------------------------------------------------------------------------
#define S1_SMEM 54272

__global__ __launch_bounds__(256)
void stage1_kernel() {
    extern __shared__ __align__(16) float s1[];
    // stage s: A at s1 + s*6784, B at s1 + s*6784 + 4608
    const int gate = blockIdx.x >> 4;
    const int col0 = (blockIdx.x & 15) << 6;
    const int m0   = blockIdx.y << 7;
    const float* Wp = g_Wall + (size_t)(3 + gate) * 1048576;

    const int tid  = threadIdx.x;
    const int wid  = tid >> 5;
    const int mrow = wid & 3;
    const int ncol = wid >> 2;

    wmma::fragment<wmma::accumulator, 16, 16, 8, float> acc[2][2];
#pragma unroll
    for (int i = 0; i < 2; i++)
#pragma unroll
        for (int j = 0; j < 2; j++) wmma::fill_fragment(acc[i][j], 0.0f);

#define S1_ISSUE(c)                                                             \
    {                                                                           \
        float* As = s1 + ((c) & 1) * 6784;                                      \
        float* Bs = As + 4608;                                                  \
        _Pragma("unroll")                                                       \
        for (int q = 0; q < 4; q++) {                                           \
            int o = tid + q * 256;                                              \
            int row = o >> 3, c4 = (o & 7) << 2;                                \
            cp16(As + row * 36 + c4,                                            \
                 g_xt + (size_t)(m0 + row) * 1024 + (c) * 32 + c4);             \
        }                                                                       \
        _Pragma("unroll")                                                       \
        for (int q = 0; q < 2; q++) {                                           \
            int o = tid + q * 256;                                              \
            int row = o >> 4, c4 = (o & 15) << 2;                               \
            cp16(Bs + row * 68 + c4,                                            \
                 Wp + (size_t)((c) * 32 + row) * 1024 + col0 + c4);             \
        }                                                                       \
    }

    S1_ISSUE(0); CP_COMMIT();

    for (int c = 0; c < 32; c++) {
        CP_WAIT0();
        __syncthreads();
        if (c < 31) { S1_ISSUE(c + 1); CP_COMMIT(); }

        const float* As = s1 + (c & 1) * 6784;
        const float* Bs = As + 4608;
#pragma unroll
        for (int kk = 0; kk < 4; kk++) {
            wmma::fragment<wmma::matrix_a, 16, 16, 8, wmma::precision::tf32, wmma::row_major> a0, a1;
            wmma::load_matrix_sync(a0, As + (mrow * 32) * 36 + kk * 8, 36);
            wmma::load_matrix_sync(a1, As + (mrow * 32 + 16) * 36 + kk * 8, 36);
            wmma::fragment<wmma::matrix_b, 16, 16, 8, wmma::precision::tf32, wmma::row_major> b0, b1;
            wmma::load_matrix_sync(b0, Bs + (kk * 8) * 68 + ncol * 32, 68);
            wmma::load_matrix_sync(b1, Bs + (kk * 8) * 68 + ncol * 32 + 16, 68);
            wmma::mma_sync(acc[0][0], a0, b0, acc[0][0]);
            wmma::mma_sync(acc[0][1], a0, b1, acc[0][1]);
            wmma::mma_sync(acc[1][0], a1, b0, acc[1][0]);
            wmma::mma_sync(acc[1][1], a1, b1, acc[1][1]);
        }
        __syncthreads();
    }
#undef S1_ISSUE

#pragma unroll
    for (int mi = 0; mi < 2; mi++)
#pragma unroll
        for (int ni = 0; ni < 2; ni++)
            wmma::store_matrix_sync(
                g_gates + (size_t)gate * TBH
                        + (size_t)(m0 + mrow * 32 + mi * 16) * 1024
                        + col0 + ncol * 32 + ni * 16,
                acc[mi][ni], 1024, wmma::mem_row_major);
}

// ---------------------------------------------------------------------------
// Persistent recurrence: 64 CTAs x 256 thr, owner-computes (CTA c: cols
// [16c,16c+16) of all 3 gates). 8 warps = 4 kgrp(K=256) x 2 mpair(32 rows).
// Split barrier: arrive after h write, prefetch next gates, then wait.
// Dyn smem 126976 B: hb[2][4][64][36] | Wb[2][4][32][52]; red=Wb, pre=hb.
// ---------------------------------------------------------------------------
#define REC_SMEM 126976

__global__ __launch_bounds__(NTHR, 1)
void recur_kernel(const float* __restrict__ b_ir, const float* __restrict__ b_hr,
                  const float* __restrict__ b_iz, const float* __restrict__ b_hz,
                  const float* __restrict__ b_in, const float* __restrict__ b_hn,
                  float* __restrict__ out, int write_hfinal) {
    extern __shared__ __align__(16) float sm[];
    float* hb  = sm;            // 2*4*64*36 = 18432 fl
    float* Wb  = sm + 18432;    // 2*4*32*52 = 13312 fl
    float* red = Wb;            // 3*64*48 = 9216 fl (post-loop alias)
    float* pre = sm;            // 64*48 = 3072 fl (post-loop alias)

    const int cta   = blockIdx.x;
    const int tid   = threadIdx.x;
    const int wid   = tid >> 5;
    const int kgrp  = wid >> 1;           // 0..3
    const int mpair = wid & 1;            // rows [32*mpair, +32)
    const int col0  = cta << 4;

    __shared__ unsigned s_gen0;
    if (tid == 0) s_gen0 = *(volatile unsigned*)&g_bar_gen;
    __syncthreads();
    const unsigned gen0 = s_gen0;

    // pointwise fixed (row,col) ownership
    const int c_pb = tid & 15;
    const int r_pb = tid >> 4;
    const int jcol = col0 + c_pb;
    const float vb_ir = b_ir[jcol], vb_hr = b_hr[jcol];
    const float vb_iz = b_iz[jcol], vb_hz = b_hz[jcol];
    const float vb_in = b_in[jcol], vb_hn = b_hn[jcol];

    // registers carried across steps
    float pg_r[4], pg_z[4], pg_n[4];      // prefetched gates for current t
    float hpq[4] = {0.f, 0.f, 0.f, 0.f};  // h_{t-1} for owned cells

    // prefetch gates for t=0
#pragma unroll
    for (int q = 0; q < 4; q++) {
        size_t gi = (size_t)(r_pb + q * 16) * 1024 + jcol;
        pg_r[q] = g_gates[gi];
        pg_z[q] = g_gates[TBH + gi];
        pg_n[q] = g_gates[2ull * TBH + gi];
    }

    for (int t = 0; t < TSZ; t++) {
        if (t > 0) {
            // ========= Phase A: hW [64 x 48] (3 gates x 16 cols) =========
            const float* hsrc = g_ht[(t - 1) & 1];

            wmma::fragment<wmma::accumulator, 16, 16, 8, float> acc[2][3];
#pragma unroll
            for (int mi = 0; mi < 2; mi++)
#pragma unroll
                for (int g = 0; g < 3; g++) wmma::fill_fragment(acc[mi][g], 0.0f);

#define R_ISSUE(c)                                                              \
            {                                                                   \
                int kofs = (c) * 32;                                            \
                _Pragma("unroll")                                               \
                for (int q = 0; q < 8; q++) {                                   \
                    int o = tid + q * 256;                                      \
                    int kg = o >> 9, idx = o & 511;                             \
                    int row = idx >> 3, c4 = (idx & 7) << 2;                    \
                    cp16(hb + (((c) & 1) * 4 + kg) * 2304 + row * 36 + c4,      \
                         hsrc + (size_t)row * 1024 + kg * 256 + kofs + c4);     \
                }                                                               \
                _Pragma("unroll")                                               \
                for (int q = 0; q < 6; q++) {                                   \
                    int o = tid + q * 256;                                      \
                    int kg = o / 384, idx = o - kg * 384;                       \
                    int row = idx / 12, cw = (idx % 12) << 2;                   \
                    int gate = cw >> 4;                                         \
                    cp16(Wb + (((c) & 1) * 4 + kg) * 1664 + row * 52 + cw,      \
                         g_Wall + (size_t)gate * 1048576                        \
                                + (size_t)(kg * 256 + kofs + row) * 1024        \
                                + col0 + (cw & 15));                            \
                }                                                               \
            }

            R_ISSUE(0); CP_COMMIT();

            for (int it = 0; it < 8; it++) {
                CP_WAIT0();
                __syncthreads();
                if (it < 7) { R_ISSUE(it + 1); CP_COMMIT(); }

                const float* A  = hb + ((it & 1) * 4 + kgrp) * 2304 + (mpair * 32) * 36;
                const float* Bp = Wb + ((it & 1) * 4 + kgrp) * 1664;
#pragma unroll
                for (int kk = 0; kk < 4; kk++) {
                    wmma::fragment<wmma::matrix_a, 16, 16, 8, wmma::precision::tf32, wmma::row_major> a0, a1;
                    wmma::load_matrix_sync(a0, A + kk * 8, 36);
                    wmma::load_matrix_sync(a1, A + 16 * 36 + kk * 8, 36);
#pragma unroll
                    for (int g = 0; g < 3; g++) {
                        wmma::fragment<wmma::matrix_b, 16, 16, 8, wmma::precision::tf32, wmma::row_major> bf;
                        wmma::load_matrix_sync(bf, Bp + (kk * 8) * 52 + g * 16, 52);
                        wmma::mma_sync(acc[0][g], a0, bf, acc[0][g]);
                        wmma::mma_sync(acc[1][g], a1, bf, acc[1][g]);
                    }
                }
                __syncthreads();
            }
#undef R_ISSUE

            // K-split reduction: kgrp 1..3 publish, kgrp 0 combines -> pre
            if (kgrp > 0) {
                float* s = red + (size_t)(kgrp - 1) * 3072;
#pragma unroll
                for (int mi = 0; mi < 2; mi++)
#pragma unroll
                    for (int g = 0; g < 3; g++)
                        wmma::store_matrix_sync(s + (mpair * 32 + mi * 16) * 48 + g * 16,
                                                acc[mi][g], 48, wmma::mem_row_major);
            }
            __syncthreads();
            if (kgrp == 0) {
#pragma unroll
                for (int src = 0; src < 3; src++) {
                    const float* s = red + (size_t)src * 3072;
#pragma unroll
                    for (int mi = 0; mi < 2; mi++)
#pragma unroll
                        for (int g = 0; g < 3; g++) {
                            wmma::fragment<wmma::accumulator, 16, 16, 8, float> p;
                            wmma::load_matrix_sync(p, s + (mpair * 32 + mi * 16) * 48 + g * 16,
                                                   48, wmma::mem_row_major);
#pragma unroll
                            for (int e = 0; e < p.num_elements; e++)
                                acc[mi][g].x[e] += p.x[e];
                        }
                }
#pragma unroll
                for (int mi = 0; mi < 2; mi++)
#pragma unroll
                    for (int g = 0; g < 3; g++)
                        wmma::store_matrix_sync(pre + (mpair * 32 + mi * 16) * 48 + g * 16,
                                                acc[mi][g], 48, wmma::mem_row_major);
            }
            __syncthreads();
        }

        // ========= Phase B: pointwise (gates & h_prev already in regs) =========
        {
            const size_t toff = (size_t)t * BH;
            float* hw = out + toff;
#pragma unroll
            for (int q = 0; q < 4; q++) {
                int row = r_pb + q * 16;
                int gi  = row * 1024 + jcol;

                float gr = pg_r[q] + vb_ir;
                float gz = pg_z[q] + vb_iz;
                float gn = pg_n[q] + vb_in;
                float hr = vb_hr, hz = vb_hz, hn = vb_hn;
                if (t > 0) {
                    hr += pre[row * 48 + c_pb];
                    hz += pre[row * 48 + 16 + c_pb];
                    hn += pre[row * 48 + 32 + c_pb];
                }
                float r = 1.0f / (1.0f + expf(-(gr + hr)));
                float z = 1.0f / (1.0f + expf(-(gz + hz)));
                float n = tanhf(gn + r * hn);
                float hnew = (1.0f - z) * n + z * hpq[q];

                hpq[q] = hnew;
                hw[gi] = hnew;
                g_ht[t & 1][gi] = wmma::__float_to_tf32(hnew);
                if (t == TSZ - 1 && write_hfinal) out[TBH + gi] = hnew;
            }
        }

        if (t == TSZ - 1) break;    // no barrier after last step

        // ========= Split barrier: arrive -> prefetch t+1 gates -> wait =========
        __syncthreads();
        const unsigned target = gen0 + (unsigned)t + 1u;
        bool released = false;
        if (tid == 0) {
            unsigned old;
            asm volatile("atom.acq_rel.gpu.add.u32 %0, [%1], %2;"
                         : "=r"(old) : "l"(&g_bar_cnt), "r"(1u) : "memory");
            if (old == NCTA - 1u) {
                asm volatile("st.relaxed.gpu.u32 [%0], %1;" :: "l"(&g_bar_cnt), "r"(0u) : "memory");
                asm volatile("st.release.gpu.u32 [%0], %1;" :: "l"(&g_bar_gen), "r"(target) : "memory");
                released = true;
            }
        }
        {   // prefetch gates for step t+1 (overlaps barrier propagation)
            const size_t toff1 = (size_t)(t + 1) * BH;
#pragma unroll
            for (int q = 0; q < 4; q++) {
                size_t gi = toff1 + (size_t)(r_pb + q * 16) * 1024 + jcol;
                pg_r[q] = g_gates[gi];
                pg_z[q] = g_gates[TBH + gi];
                pg_n[q] = g_gates[2ull * TBH + gi];
            }
        }
        if (tid == 0 && !released) {
            unsigned v;
            do {
                asm volatile("ld.acquire.gpu.u32 %0, [%1];" : "=r"(v) : "l"(&g_bar_gen) : "memory");
            } while ((int)(v - target) < 0);
        }
        __syncthreads();
    }
}

// ---------------------------------------------------------------------------
extern "C" void kernel_launch(void* const* d_in, const int* in_sizes, int n_in,
                              void* d_out, int out_size) {
    const float* x    = (const float*)d_in[0];
    const float* W_ir = (const float*)d_in[1];
    const float* b_ir = (const float*)d_in[2];
    const float* W_hr = (const float*)d_in[3];
    const float* b_hr = (const float*)d_in[4];
    const float* W_iz = (const float*)d_in[5];
    const float* b_iz = (const float*)d_in[6];
    const float* W_hz = (const float*)d_in[7];
    const float* b_hz = (const float*)d_in[8];
    const float* W_in = (const float*)d_in[9];
    const float* b_in = (const float*)d_in[10];
    const float* W_hn = (const float*)d_in[11];
    const float* b_hn = (const float*)d_in[12];
    float* out = (float*)d_out;

    const int has_hfinal = ((size_t)out_size >= TBH + (size_t)BH) ? 1 : 0;

    static int attr_done = 0;
    if (!attr_done) {
        cudaFuncSetAttribute(recur_kernel,
                             cudaFuncAttributeMaxDynamicSharedMemorySize, REC_SMEM);
        cudaFuncSetAttribute(stage1_kernel,
                             cudaFuncAttributeMaxDynamicSharedMemorySize, S1_SMEM);
        attr_done = 1;
    }

    // prep: tf32 weights + transposed tf32 x
    wconv_kernel<<<1024, 256>>>(W_hr, 0);
    wconv_kernel<<<1024, 256>>>(W_hz, 1);
    wconv_kernel<<<1024, 256>>>(W_hn, 2);
    wconv_kernel<<<1024, 256>>>(W_ir, 3);
    wconv_kernel<<<1024, 256>>>(W_iz, 4);
    wconv_kernel<<<1024, 256>>>(W_in, 5);
    xprep_kernel<<<32768, 256>>>(x);

    stage1_kernel<<<dim3(48, 256), 256, S1_SMEM>>>();

    recur_kernel<<<NCTA, NTHR, REC_SMEM>>>(
        b_ir, b_hr, b_iz, b_hz, b_in, b_hn, out, has_hfinal);
}